// round 14
// baseline (speedup 1.0000x reference)
#include <cuda_runtime.h>
#include <cstdint>

#define BB 128
#define PP 8732
#define CC 21
#define OO 32
#define NT 1024
#define NW 32
#define NTILES 9        // ceil(8732/1024), tail = 540 rows
#define KMASK 0xFFFFFFC0u   // top 26 bits of iou; low 6 = tie-break payload

typedef unsigned long long u64;

// ---------------- global accumulators (zero-init; self-resetting) ----------------
__device__ double g_pos_sum, g_loc_sum, g_hard_sum;
__device__ int    g_npos_total, g_done;

// ---------------- shared memory layout ----------------
struct __align__(16) SmemLayout {
    float  tile[2][NT * CC];            // 172032B double-buffered score tiles
    u64    wobj[NW * OO];               // per-warp per-object (masked_iou<<32)|~p
    unsigned wobj2[NW * 5 * OO];        // per-(warp,chunk,object) redux winner key
    float4 box[OO];
    float  area[OO];
    float  bcx[OO], bcy[OO], bw[OO], bh[OO];
    int    labels[OO];
    int    pfeo[OO];
    float  rf1[NW], rf2[NW];
    int    ri[NW];
    alignas(16) unsigned cntw[2][NW];
    int    npb;
    unsigned char ofep[PP];             // obj idx (0..31) | keep flag (bit 7)
};

__device__ __forceinline__ void cp_async16(uint32_t dst, const void* src) {
    asm volatile("cp.async.cg.shared.global [%0], [%1], 16;\n" :: "r"(dst), "l"(src));
}
__device__ __forceinline__ void cp_commit() { asm volatile("cp.async.commit_group;\n"); }
template <int N>
__device__ __forceinline__ void cp_wait() {
    asm volatile("cp.async.wait_group %0;\n" :: "n"(N));
}
__device__ __forceinline__ float frcp(float b) {
    float r;
    asm("rcp.approx.f32 %0, %1;" : "=f"(r) : "f"(b));
    return r;
}

// Matching for chunk c (strides 2c, 2c+1): per-prior argmax -> ofep,
// per-object warp winner -> wobj2[(warp*5+c)*OO + o].  (R7/R10-proven core)
__device__ __forceinline__ void match_pair(SmemLayout& sm, const float4* __restrict__ pri4,
                                           int c, int tid, int warp, int lane,
                                           unsigned inv0, unsigned inv1, bool lp)
{
    const int base = c * 2 * NT;
    float4 p0 = pri4[base + tid];
    float4 p1 = pri4[base + NT + tid];
    const float ax0 = fmaf(p0.z, -0.5f, p0.x), ax1 = fmaf(p0.z, 0.5f, p0.x);
    const float ay0 = fmaf(p0.w, -0.5f, p0.y), ay1 = fmaf(p0.w, 0.5f, p0.y);
    const float apa = (ax1 - ax0) * (ay1 - ay0);
    const float cx0 = fmaf(p1.z, -0.5f, p1.x), cx1 = fmaf(p1.z, 0.5f, p1.x);
    const float cy0 = fmaf(p1.w, -0.5f, p1.y), cy1 = fmaf(p1.w, 0.5f, p1.y);
    const float cpa = (cx1 - cx0) * (cy1 - cy0);

    unsigned bibA = 0u, bibB = 0u;
    const int widx = (warp * 5 + c) * OO;

    #pragma unroll 8
    for (int o = 0; o < OO; ++o) {
        const float4 bx = sm.box[o];
        const float  ar = sm.area[o];
        // slot 0
        float lox = fmaxf(bx.x, ax0), loy = fmaxf(bx.y, ay0);
        float hix = fminf(bx.z, ax1), hiy = fminf(bx.w, ay1);
        float dx  = fmaxf(hix - lox, 0.0f), dy = fmaxf(hiy - loy, 0.0f);
        float in0 = dx * dy;
        float un0 = (apa + ar) - in0;
        unsigned u0 = __float_as_uint(in0 * frcp(un0));
        // slot 1
        lox = fmaxf(bx.x, cx0); loy = fmaxf(bx.y, cy0);
        hix = fminf(bx.z, cx1); hiy = fminf(bx.w, cy1);
        dx  = fmaxf(hix - lox, 0.0f); dy = fmaxf(hiy - loy, 0.0f);
        float in1 = dx * dy;
        float un1 = (cpa + ar) - in1;
        unsigned u1 = __float_as_uint(in1 * frcp(un1));

        bibA = max(bibA, (u0 & KMASK) | (unsigned)(63 - o));
        bibB = max(bibB, (u1 & KMASK) | (unsigned)(63 - o));

        unsigned km = max((u0 & KMASK) | inv0, (u1 & KMASK) | inv1);
        unsigned r  = __reduce_max_sync(0xffffffffu, km);
        if (lp) sm.wobj2[widx + o] = r;
    }
    sm.ofep[base + tid]      = (unsigned char)((63 - (bibA & 63)) | (bibA >= 0x3F000000u ? 0x80 : 0));
    sm.ofep[base + NT + tid] = (unsigned char)((63 - (bibB & 63)) | (bibB >= 0x3F000000u ? 0x80 : 0));
}

__device__ __forceinline__ void match_tail(SmemLayout& sm, const float4* __restrict__ pri4,
                                           int tid, int warp, unsigned inv0, bool lp)
{
    const int p = 8 * NT + tid;
    const bool valid = p < PP;
    float4 pr = valid ? pri4[p] : make_float4(2e9f, 2e9f, 0.0f, 0.0f);
    const float ax0 = fmaf(pr.z, -0.5f, pr.x), ax1 = fmaf(pr.z, 0.5f, pr.x);
    const float ay0 = fmaf(pr.w, -0.5f, pr.y), ay1 = fmaf(pr.w, 0.5f, pr.y);
    const float apa = (ax1 - ax0) * (ay1 - ay0);

    unsigned bib = 0u;
    const int widx = (warp * 5 + 4) * OO;
    #pragma unroll 8
    for (int o = 0; o < OO; ++o) {
        const float4 bx = sm.box[o];
        const float  ar = sm.area[o];
        float lox = fmaxf(bx.x, ax0), loy = fmaxf(bx.y, ay0);
        float hix = fminf(bx.z, ax1), hiy = fminf(bx.w, ay1);
        float dx  = fmaxf(hix - lox, 0.0f), dy = fmaxf(hiy - loy, 0.0f);
        float in0 = dx * dy;
        float un0 = (apa + ar) - in0;
        unsigned u0 = __float_as_uint(in0 * frcp(un0));
        bib = max(bib, (u0 & KMASK) | (unsigned)(63 - o));
        unsigned r = __reduce_max_sync(0xffffffffu, (u0 & KMASK) | inv0);
        if (lp) sm.wobj2[widx + o] = r;
    }
    if (valid)
        sm.ofep[p] = (unsigned char)((63 - (bib & 63)) | (bib >= 0x3F000000u ? 0x80 : 0));
}

__global__ __launch_bounds__(NT)
void mbl_kernel(const float* __restrict__ locs,
                const float* __restrict__ scores,
                const float* __restrict__ boxes,
                const int*   __restrict__ labels,
                const float* __restrict__ priors,
                float*       __restrict__ out)
{
    extern __shared__ unsigned char smraw[];
    SmemLayout& sm = *reinterpret_cast<SmemLayout*>(smraw);

    const int b    = blockIdx.x;
    const int tid  = threadIdx.x;
    const int warp = tid >> 5;
    const int lane = tid & 31;
    const bool lp  = (lane == 0);
    const unsigned inv0 = (unsigned)(63 - lane);   // slot0: bit5 set
    const unsigned inv1 = (unsigned)(31 - lane);   // slot1

    if (tid < OO) {
        const float* bp = boxes + ((size_t)b * OO + tid) * 4;
        float x0 = bp[0], y0 = bp[1], x1 = bp[2], y1 = bp[3];
        sm.box[tid]  = make_float4(x0, y0, x1, y1);
        sm.area[tid] = (x1 - x0) * (y1 - y0);
        sm.bcx[tid] = (x0 + x1) * 0.5f;
        sm.bcy[tid] = (y0 + y1) * 0.5f;
        sm.bw[tid]  = x1 - x0;
        sm.bh[tid]  = y1 - y0;
        sm.labels[tid] = labels[(size_t)b * OO + tid];
    }
    __syncthreads();

    const float4* pri4  = reinterpret_cast<const float4*>(priors);
    const float4* locs4 = reinterpret_cast<const float4*>(locs);

    uint32_t tbase[2];
    tbase[0] = (uint32_t)__cvta_generic_to_shared(&sm.tile[0][0]);
    tbase[1] = (uint32_t)__cvta_generic_to_shared(&sm.tile[1][0]);

    // Per-warp staging: warp w copies ONLY its own 32 rows (2688B segment,
    // 16B-aligned both sides). Buffer regions warp-private -> no block barriers.
    auto issue_tile_w = [&](int t) {
        const int rowbase = t * NT + warp * 32;
        const int nrows   = min(32, PP - rowbase);
        if (nrows > 0) {
            const int nbytes = nrows * (CC * 4);          // 84*n, n%4==0 -> /16 exact
            const char* src = reinterpret_cast<const char*>(
                scores + ((size_t)b * PP + rowbase) * CC);
            const uint32_t dst = tbase[t & 1] + warp * (32 * CC * 4);
            for (int i = lane * 16; i < nbytes; i += 32 * 16)
                cp_async16(dst + i, src + i);
        }
        cp_commit();                                       // uniform group count
    };
    issue_tile_w(0);
    issue_tile_w(1);

    unsigned nb[NTILES];
    auto lse_tile = [&](int t) -> unsigned {
        const float* row = &sm.tile[t & 1][tid * CC];
        float s0 = 0.0f, s1 = 0.0f, s2 = 0.0f;
        #pragma unroll
        for (int cc = 0; cc < 7; ++cc) {
            s0 += __expf(row[3 * cc]);
            s1 += __expf(row[3 * cc + 1]);
            s2 += __expf(row[3 * cc + 2]);
        }
        float conf = __logf(s0 + s1 + s2) - row[0];
        return (conf > 0.0f) ? __float_as_uint(conf) : 0u;
    };

    // ======== fused: matching chunk c -> CE tiles 2c, 2c+1 (warp-autonomous) =========
    #pragma unroll
    for (int c = 0; c < 4; ++c) {
        match_pair(sm, pri4, c, tid, warp, lane, inv0, inv1, lp);

        cp_wait<1>(); __syncwarp();
        nb[2 * c] = lse_tile(2 * c);
        issue_tile_w(2 * c + 2);

        cp_wait<1>(); __syncwarp();
        nb[2 * c + 1] = lse_tile(2 * c + 1);
        if (2 * c + 3 < NTILES) issue_tile_w(2 * c + 3);
    }
    if (warp < 17) {
        match_tail(sm, pri4, tid, warp, inv0, lp);   // only warps with valid tail priors
    } else if (lp) {
        sm.wobj2[(warp * 5 + 4) * OO + lane] = 0u;   // lane0 writes its own row? no:
    }
    if (warp >= 17) {                                 // neutral keys for skipped chunk
        sm.wobj2[(warp * 5 + 4) * OO + lane] = 0u;   // all 32 entries of this warp's row
    }
    cp_wait<0>(); __syncwarp();
    nb[8] = (tid < PP - 8 * NT) ? lse_tile(8) : 0u;

    // ======== per-object resolution: chunk-scan -> 64-bit key -> cross-warp ==========
    __syncwarp();     // wobj2 rows are warp-private (written by lanes of same warp)
    {
        const unsigned* rr = &sm.wobj2[warp * 5 * OO + lane];
        unsigned best = rr[0]; int bc = 0;
        #pragma unroll
        for (int c = 1; c < 5; ++c) {
            unsigned r = rr[c * OO];
            if ((r & KMASK) > (best & KMASK)) { best = r; bc = c; }
        }
        int sdec = 1 - ((best >> 5) & 1);
        int p = bc * 2 * NT + sdec * NT + warp * 32 + (31 - (int)(best & 31));
        sm.wobj[warp * OO + lane] =
            ((u64)(best & KMASK) << 32) | (unsigned)(~p);
    }
    __syncthreads();
    if (tid < OO) {
        u64 bestk = sm.wobj[tid];
        #pragma unroll
        for (int w = 1; w < NW; ++w) {
            u64 k = sm.wobj[w * OO + tid];
            if (k > bestk) bestk = k;
        }
        sm.pfeo[tid] = (int)(~(unsigned)bestk);
    }
    __syncthreads();
    if (tid == 0) {            // sequential: last object wins on duplicate priors
        for (int o = 0; o < OO; ++o)
            sm.ofep[sm.pfeo[o]] = (unsigned char)(o | 0x80);
    }
    __syncthreads();

    // ======== positives post-pass: fix nb, accumulate posc/locsum/np =================
    float posc = 0.0f, locsum = 0.0f; int np = 0;
    #pragma unroll
    for (int j = 0; j < NTILES; ++j) {
        const int p = j * NT + tid;
        if (j < 8 || p < PP) {
            unsigned pk = sm.ofep[p];
            if (pk & 0x80) {
                int o   = pk & 31;
                int lab = sm.labels[o];
                if (lab != 0) {
                    const float* srow = scores + ((size_t)b * PP + p) * CC;
                    float r0 = __ldg(srow);
                    float rl = __ldg(srow + lab);
                    posc += __uint_as_float(nb[j]) + r0 - rl;
                    np++;
                    nb[j] = 0u;
                    float4 pr = pri4[p];
                    float rz = frcp(pr.z), rw = frcp(pr.w);
                    float gx = (sm.bcx[o] - pr.x) * 10.0f * rz;
                    float gy = (sm.bcy[o] - pr.y) * 10.0f * rw;
                    float gw = __logf(sm.bw[o] * rz) * 5.0f;
                    float gh = __logf(sm.bh[o] * rw) * 5.0f;
                    float4 pl = locs4[(size_t)b * PP + p];
                    locsum += fabsf(pl.x - gx) + fabsf(pl.y - gy)
                            + fabsf(pl.z - gw) + fabsf(pl.w - gh);
                }
            }
        }
    }

    // ---- block reduce np / posc / locsum ----
    #pragma unroll
    for (int off = 16; off > 0; off >>= 1) {
        posc   += __shfl_down_sync(0xffffffffu, posc,   off);
        locsum += __shfl_down_sync(0xffffffffu, locsum, off);
        np     += __shfl_down_sync(0xffffffffu, np,     off);
    }
    if (lane == 0) { sm.rf1[warp] = posc; sm.rf2[warp] = locsum; sm.ri[warp] = np; }
    __syncthreads();
    if (tid == 0) {
        float pc = 0.0f, ls = 0.0f; int n = 0;
        #pragma unroll
        for (int w = 0; w < NW; ++w) { pc += sm.rf1[w]; ls += sm.rf2[w]; n += sm.ri[w]; }
        sm.npb = n;
        atomicAdd(&g_npos_total, n);
        atomicAdd(&g_pos_sum, (double)pc);
        atomicAdd(&g_loc_sum, (double)ls);
    }
    __syncthreads();

    // ======== Exact top-k: ternary (2-probe) bit-pattern search =======================
    const int k = min(3 * sm.npb, PP);
    if (k > 0) {
        unsigned lo = 0u, hi = 0x43800000u;       // [0, 256)
        for (int itr = 0; itr < 22 && (hi - lo) > 1u; ++itr) {
            unsigned d  = hi - lo;
            unsigned t1 = d / 3u; if (t1 == 0u) t1 = 1u;
            unsigned m1 = lo + t1;
            unsigned m2 = lo + 2u * t1;
            if (m2 >= hi) m2 = hi - 1u;
            if (m2 < m1)  m2 = m1;
            unsigned c = 0;
            #pragma unroll
            for (int j = 0; j < NTILES; ++j) {
                c += (nb[j] >= m1) ? 1u : 0u;
                c += (nb[j] >= m2) ? 0x10000u : 0u;
            }
            c = __reduce_add_sync(0xffffffffu, c);
            if (lane == 0) sm.cntw[itr & 1][warp] = c;
            __syncthreads();
            const uint4* c4 = reinterpret_cast<const uint4*>(sm.cntw[itr & 1]);
            unsigned tot = 0;
            #pragma unroll
            for (int i = 0; i < NW / 4; ++i) {
                uint4 v = c4[i];
                tot += v.x + v.y + v.z + v.w;
            }
            const int c1 = (int)(tot & 0xFFFFu);
            const int c2 = (int)(tot >> 16);
            if (c2 >= k)      lo = m2;
            else if (c1 >= k) { lo = m1; hi = m2; }
            else              hi = m1;
        }
        const unsigned lov = lo;
        const float V = __uint_as_float(lov);
        float psum = 0.0f; int pcnt = 0;
        #pragma unroll
        for (int j = 0; j < NTILES; ++j)
            if (nb[j] > lov) { psum += __uint_as_float(nb[j]); pcnt++; }
        #pragma unroll
        for (int off = 16; off > 0; off >>= 1) {
            psum += __shfl_down_sync(0xffffffffu, psum, off);
            pcnt += __shfl_down_sync(0xffffffffu, pcnt, off);
        }
        if (lane == 0) { sm.rf1[warp] = psum; sm.ri[warp] = pcnt; }
        __syncthreads();
        if (tid == 0) {
            double hs = 0.0; int cg = 0;
            #pragma unroll
            for (int w = 0; w < NW; ++w) { hs += (double)sm.rf1[w]; cg += sm.ri[w]; }
            hs += (double)(k - cg) * (double)V;
            atomicAdd(&g_hard_sum, hs);
        }
    }

    // ======== last-block finalize + self-reset =========================================
    if (tid == 0) {
        __threadfence();
        int ticket = atomicAdd(&g_done, 1);
        if (ticket == BB - 1) {
            double ps = atomicAdd(&g_pos_sum,  0.0);
            double hs = atomicAdd(&g_hard_sum, 0.0);
            double ls = atomicAdd(&g_loc_sum,  0.0);
            int    nn = atomicAdd(&g_npos_total, 0);
            double n  = (double)nn;
            out[0] = (float)((ps + hs) / n + ls / (n * 4.0));
            atomicExch((unsigned long long*)&g_pos_sum,  0ull);
            atomicExch((unsigned long long*)&g_hard_sum, 0ull);
            atomicExch((unsigned long long*)&g_loc_sum,  0ull);
            atomicExch(&g_npos_total, 0);
            __threadfence();
            atomicExch(&g_done, 0);
        }
    }
}

extern "C" void kernel_launch(void* const* d_in, const int* in_sizes, int n_in,
                              void* d_out, int out_size) {
    const float* locs   = (const float*)d_in[0];
    const float* scores = (const float*)d_in[1];
    const float* boxes  = (const float*)d_in[2];
    const int*   labels = (const int*)  d_in[3];
    const float* priors = (const float*)d_in[4];
    float* out = (float*)d_out;

    cudaFuncSetAttribute(mbl_kernel, cudaFuncAttributeMaxDynamicSharedMemorySize,
                         (int)sizeof(SmemLayout));
    mbl_kernel<<<BB, NT, sizeof(SmemLayout)>>>(locs, scores, boxes, labels, priors, out);
}

// round 15
// speedup vs baseline: 1.5963x; 1.5963x over previous
#include <cuda_runtime.h>
#include <cstdint>

#define BB 128
#define PP 8732
#define CC 21
#define OO 32
#define NT 1024
#define NW 32
#define NTILES 9        // ceil(8732/1024), tail = 540 rows
#define KMASK 0xFFFFFFC0u   // top 26 bits of iou; low 6 = tie-break payload

typedef unsigned long long u64;

// ---------------- global accumulators (zero-init; self-resetting) ----------------
__device__ double g_pos_sum, g_loc_sum, g_hard_sum;
__device__ int    g_npos_total, g_done;

// ---------------- shared memory layout ----------------
struct __align__(16) SmemLayout {
    float  tile[2][NT * CC];            // 172032B double-buffered score tiles
    u64    wobj[NW * OO];               // per-warp per-object (masked_iou<<32)|~p
    unsigned wobj2[NW * 5 * OO];        // per-(warp,chunk,object) redux winner key
    float4 box[OO];
    float  area[OO];
    float  bcx[OO], bcy[OO], bw[OO], bh[OO];
    int    labels[OO];
    int    pfeo[OO];
    float  rf1[NW], rf2[NW];
    int    ri[NW];
    alignas(16) unsigned cntw[2][NW];
    int    npb;
    unsigned char ofep[PP];             // obj idx (0..31) | keep flag (bit 7)
};

__device__ __forceinline__ void cp_async16(uint32_t dst, const void* src) {
    asm volatile("cp.async.cg.shared.global [%0], [%1], 16;\n" :: "r"(dst), "l"(src));
}
__device__ __forceinline__ void cp_commit() { asm volatile("cp.async.commit_group;\n"); }
template <int N>
__device__ __forceinline__ void cp_wait() {
    asm volatile("cp.async.wait_group %0;\n" :: "n"(N));
}
__device__ __forceinline__ float frcp(float b) {
    float r;
    asm("rcp.approx.f32 %0, %1;" : "=f"(r) : "f"(b));
    return r;
}

// Matching for chunk c (strides 2c, 2c+1): per-prior argmax -> ofep,
// per-object warp winner -> wobj2[(warp*5+c)*OO + o].  (R7/R10-proven core)
__device__ __forceinline__ void match_pair(SmemLayout& sm, const float4* __restrict__ pri4,
                                           int c, int tid, int warp, int lane,
                                           unsigned inv0, unsigned inv1, bool lp)
{
    const int base = c * 2 * NT;
    float4 p0 = pri4[base + tid];
    float4 p1 = pri4[base + NT + tid];
    const float ax0 = fmaf(p0.z, -0.5f, p0.x), ax1 = fmaf(p0.z, 0.5f, p0.x);
    const float ay0 = fmaf(p0.w, -0.5f, p0.y), ay1 = fmaf(p0.w, 0.5f, p0.y);
    const float apa = (ax1 - ax0) * (ay1 - ay0);
    const float cx0 = fmaf(p1.z, -0.5f, p1.x), cx1 = fmaf(p1.z, 0.5f, p1.x);
    const float cy0 = fmaf(p1.w, -0.5f, p1.y), cy1 = fmaf(p1.w, 0.5f, p1.y);
    const float cpa = (cx1 - cx0) * (cy1 - cy0);

    unsigned bibA = 0u, bibB = 0u;
    const int widx = (warp * 5 + c) * OO;

    #pragma unroll 8
    for (int o = 0; o < OO; ++o) {
        const float4 bx = sm.box[o];
        const float  ar = sm.area[o];
        // slot 0
        float lox = fmaxf(bx.x, ax0), loy = fmaxf(bx.y, ay0);
        float hix = fminf(bx.z, ax1), hiy = fminf(bx.w, ay1);
        float dx  = fmaxf(hix - lox, 0.0f), dy = fmaxf(hiy - loy, 0.0f);
        float in0 = dx * dy;
        float un0 = (apa + ar) - in0;
        unsigned u0 = __float_as_uint(in0 * frcp(un0));
        // slot 1
        lox = fmaxf(bx.x, cx0); loy = fmaxf(bx.y, cy0);
        hix = fminf(bx.z, cx1); hiy = fminf(bx.w, cy1);
        dx  = fmaxf(hix - lox, 0.0f); dy = fmaxf(hiy - loy, 0.0f);
        float in1 = dx * dy;
        float un1 = (cpa + ar) - in1;
        unsigned u1 = __float_as_uint(in1 * frcp(un1));

        bibA = max(bibA, (u0 & KMASK) | (unsigned)(63 - o));
        bibB = max(bibB, (u1 & KMASK) | (unsigned)(63 - o));

        unsigned km = max((u0 & KMASK) | inv0, (u1 & KMASK) | inv1);
        unsigned r  = __reduce_max_sync(0xffffffffu, km);
        if (lp) sm.wobj2[widx + o] = r;
    }
    sm.ofep[base + tid]      = (unsigned char)((63 - (bibA & 63)) | (bibA >= 0x3F000000u ? 0x80 : 0));
    sm.ofep[base + NT + tid] = (unsigned char)((63 - (bibB & 63)) | (bibB >= 0x3F000000u ? 0x80 : 0));
}

__device__ __forceinline__ void match_tail(SmemLayout& sm, const float4* __restrict__ pri4,
                                           int tid, int warp, unsigned inv0, bool lp)
{
    const int p = 8 * NT + tid;
    const bool valid = p < PP;
    float4 pr = valid ? pri4[p] : make_float4(2e9f, 2e9f, 0.0f, 0.0f);
    const float ax0 = fmaf(pr.z, -0.5f, pr.x), ax1 = fmaf(pr.z, 0.5f, pr.x);
    const float ay0 = fmaf(pr.w, -0.5f, pr.y), ay1 = fmaf(pr.w, 0.5f, pr.y);
    const float apa = (ax1 - ax0) * (ay1 - ay0);

    unsigned bib = 0u;
    const int widx = (warp * 5 + 4) * OO;
    #pragma unroll 8
    for (int o = 0; o < OO; ++o) {
        const float4 bx = sm.box[o];
        const float  ar = sm.area[o];
        float lox = fmaxf(bx.x, ax0), loy = fmaxf(bx.y, ay0);
        float hix = fminf(bx.z, ax1), hiy = fminf(bx.w, ay1);
        float dx  = fmaxf(hix - lox, 0.0f), dy = fmaxf(hiy - loy, 0.0f);
        float in0 = dx * dy;
        float un0 = (apa + ar) - in0;
        unsigned u0 = __float_as_uint(in0 * frcp(un0));
        bib = max(bib, (u0 & KMASK) | (unsigned)(63 - o));
        unsigned r = __reduce_max_sync(0xffffffffu, (u0 & KMASK) | inv0);
        if (lp) sm.wobj2[widx + o] = r;
    }
    if (valid)
        sm.ofep[p] = (unsigned char)((63 - (bib & 63)) | (bib >= 0x3F000000u ? 0x80 : 0));
}

__global__ __launch_bounds__(NT)
void mbl_kernel(const float* __restrict__ locs,
                const float* __restrict__ scores,
                const float* __restrict__ boxes,
                const int*   __restrict__ labels,
                const float* __restrict__ priors,
                float*       __restrict__ out)
{
    extern __shared__ unsigned char smraw[];
    SmemLayout& sm = *reinterpret_cast<SmemLayout*>(smraw);

    const int b    = blockIdx.x;
    const int tid  = threadIdx.x;
    const int warp = tid >> 5;
    const int lane = tid & 31;
    const bool lp  = (lane == 0);
    const unsigned inv0 = (unsigned)(63 - lane);   // slot0: bit5 set
    const unsigned inv1 = (unsigned)(31 - lane);   // slot1

    if (tid < OO) {
        const float* bp = boxes + ((size_t)b * OO + tid) * 4;
        float x0 = bp[0], y0 = bp[1], x1 = bp[2], y1 = bp[3];
        sm.box[tid]  = make_float4(x0, y0, x1, y1);
        sm.area[tid] = (x1 - x0) * (y1 - y0);
        sm.bcx[tid] = (x0 + x1) * 0.5f;
        sm.bcy[tid] = (y0 + y1) * 0.5f;
        sm.bw[tid]  = x1 - x0;
        sm.bh[tid]  = y1 - y0;
        sm.labels[tid] = labels[(size_t)b * OO + tid];
    }
    __syncthreads();

    const float4* pri4  = reinterpret_cast<const float4*>(priors);
    const float4* locs4 = reinterpret_cast<const float4*>(locs);

    uint32_t tbase[2];
    tbase[0] = (uint32_t)__cvta_generic_to_shared(&sm.tile[0][0]);
    tbase[1] = (uint32_t)__cvta_generic_to_shared(&sm.tile[1][0]);

    // Per-warp staging: warp w copies ONLY its own 32 rows (2688B segment,
    // 16B-aligned both sides). Buffer regions warp-private -> no block barriers.
    auto issue_tile_w = [&](int t) {
        const int rowbase = t * NT + warp * 32;
        const int nrows   = min(32, PP - rowbase);
        if (nrows > 0) {
            const int nbytes = nrows * (CC * 4);          // 84*n, n%4==0 -> /16 exact
            const char* src = reinterpret_cast<const char*>(
                scores + ((size_t)b * PP + rowbase) * CC);
            const uint32_t dst = tbase[t & 1] + warp * (32 * CC * 4);
            for (int i = lane * 16; i < nbytes; i += 32 * 16)
                cp_async16(dst + i, src + i);
        }
        cp_commit();                                       // uniform group count
    };
    issue_tile_w(0);
    issue_tile_w(1);

    unsigned nb[NTILES];
    auto lse_tile = [&](int t) -> unsigned {
        const float* row = &sm.tile[t & 1][tid * CC];
        float s0 = 0.0f, s1 = 0.0f, s2 = 0.0f;
        #pragma unroll
        for (int cc = 0; cc < 7; ++cc) {
            s0 += __expf(row[3 * cc]);
            s1 += __expf(row[3 * cc + 1]);
            s2 += __expf(row[3 * cc + 2]);
        }
        float conf = __logf(s0 + s1 + s2) - row[0];
        return (conf > 0.0f) ? __float_as_uint(conf) : 0u;
    };

    // ======== fused: matching chunk c -> CE tiles 2c, 2c+1 (warp-autonomous) =========
    #pragma unroll
    for (int c = 0; c < 4; ++c) {
        match_pair(sm, pri4, c, tid, warp, lane, inv0, inv1, lp);

        cp_wait<1>(); __syncwarp();
        nb[2 * c] = lse_tile(2 * c);
        issue_tile_w(2 * c + 2);

        cp_wait<1>(); __syncwarp();
        nb[2 * c + 1] = lse_tile(2 * c + 1);
        if (2 * c + 3 < NTILES) issue_tile_w(2 * c + 3);
    }
    if (warp < 17) {
        match_tail(sm, pri4, tid, warp, inv0, lp);   // only warps with valid tail priors
    } else {
        sm.wobj2[(warp * 5 + 4) * OO + lane] = 0u;   // neutral key for skipped chunk
    }
    cp_wait<0>(); __syncwarp();
    nb[8] = (tid < PP - 8 * NT) ? lse_tile(8) : 0u;

    // ======== per-object resolution: chunk-scan -> 64-bit key -> cross-warp ==========
    __syncwarp();     // wobj2 rows are warp-private (written by lanes of same warp)
    {
        const unsigned* rr = &sm.wobj2[warp * 5 * OO + lane];
        unsigned best = rr[0]; int bc = 0;
        #pragma unroll
        for (int c = 1; c < 5; ++c) {
            unsigned r = rr[c * OO];
            if ((r & KMASK) > (best & KMASK)) { best = r; bc = c; }
        }
        int sdec = 1 - ((best >> 5) & 1);
        int p = bc * 2 * NT + sdec * NT + warp * 32 + (31 - (int)(best & 31));
        sm.wobj[warp * OO + lane] =
            ((u64)(best & KMASK) << 32) | (unsigned)(~p);
    }
    __syncthreads();
    if (tid < OO) {
        u64 bestk = sm.wobj[tid];
        #pragma unroll
        for (int w = 1; w < NW; ++w) {
            u64 k = sm.wobj[w * OO + tid];
            if (k > bestk) bestk = k;
        }
        sm.pfeo[tid] = (int)(~(unsigned)bestk);
    }
    __syncthreads();
    if (tid == 0) {            // sequential: last object wins on duplicate priors
        for (int o = 0; o < OO; ++o)
            sm.ofep[sm.pfeo[o]] = (unsigned char)(o | 0x80);
    }
    __syncthreads();

    // ======== positives post-pass: fix nb, accumulate posc/locsum/np =================
    float posc = 0.0f, locsum = 0.0f; int np = 0;
    #pragma unroll
    for (int j = 0; j < NTILES; ++j) {
        const int p = j * NT + tid;
        if (j < 8 || p < PP) {
            unsigned pk = sm.ofep[p];
            if (pk & 0x80) {
                int o   = pk & 31;
                int lab = sm.labels[o];
                if (lab != 0) {
                    const float* srow = scores + ((size_t)b * PP + p) * CC;
                    float r0 = __ldg(srow);
                    float rl = __ldg(srow + lab);
                    posc += __uint_as_float(nb[j]) + r0 - rl;
                    np++;
                    nb[j] = 0u;
                    float4 pr = pri4[p];
                    float rz = frcp(pr.z), rw = frcp(pr.w);
                    float gx = (sm.bcx[o] - pr.x) * 10.0f * rz;
                    float gy = (sm.bcy[o] - pr.y) * 10.0f * rw;
                    float gw = __logf(sm.bw[o] * rz) * 5.0f;
                    float gh = __logf(sm.bh[o] * rw) * 5.0f;
                    float4 pl = locs4[(size_t)b * PP + p];
                    locsum += fabsf(pl.x - gx) + fabsf(pl.y - gy)
                            + fabsf(pl.z - gw) + fabsf(pl.w - gh);
                }
            }
        }
    }

    // ---- block reduce np / posc / locsum ----
    #pragma unroll
    for (int off = 16; off > 0; off >>= 1) {
        posc   += __shfl_down_sync(0xffffffffu, posc,   off);
        locsum += __shfl_down_sync(0xffffffffu, locsum, off);
        np     += __shfl_down_sync(0xffffffffu, np,     off);
    }
    if (lane == 0) { sm.rf1[warp] = posc; sm.rf2[warp] = locsum; sm.ri[warp] = np; }
    __syncthreads();
    if (tid == 0) {
        float pc = 0.0f, ls = 0.0f; int n = 0;
        #pragma unroll
        for (int w = 0; w < NW; ++w) { pc += sm.rf1[w]; ls += sm.rf2[w]; n += sm.ri[w]; }
        sm.npb = n;
        atomicAdd(&g_npos_total, n);
        atomicAdd(&g_pos_sum, (double)pc);
        atomicAdd(&g_loc_sum, (double)ls);
    }
    __syncthreads();

    // ======== Exact top-k: ternary (2-probe) bit-pattern search =======================
    const int k = min(3 * sm.npb, PP);
    if (k > 0) {
        unsigned lo = 0u, hi = 0x43800000u;       // [0, 256)
        for (int itr = 0; itr < 22 && (hi - lo) > 1u; ++itr) {
            unsigned d  = hi - lo;
            unsigned t1 = d / 3u; if (t1 == 0u) t1 = 1u;
            unsigned m1 = lo + t1;
            unsigned m2 = lo + 2u * t1;
            if (m2 >= hi) m2 = hi - 1u;
            if (m2 < m1)  m2 = m1;
            unsigned c = 0;
            #pragma unroll
            for (int j = 0; j < NTILES; ++j) {
                c += (nb[j] >= m1) ? 1u : 0u;
                c += (nb[j] >= m2) ? 0x10000u : 0u;
            }
            c = __reduce_add_sync(0xffffffffu, c);
            if (lane == 0) sm.cntw[itr & 1][warp] = c;
            __syncthreads();
            const uint4* c4 = reinterpret_cast<const uint4*>(sm.cntw[itr & 1]);
            unsigned tot = 0;
            #pragma unroll
            for (int i = 0; i < NW / 4; ++i) {
                uint4 v = c4[i];
                tot += v.x + v.y + v.z + v.w;
            }
            const int c1 = (int)(tot & 0xFFFFu);
            const int c2 = (int)(tot >> 16);
            if (c2 >= k)      lo = m2;
            else if (c1 >= k) { lo = m1; hi = m2; }
            else              hi = m1;
        }
        const unsigned lov = lo;
        const float V = __uint_as_float(lov);
        float psum = 0.0f; int pcnt = 0;
        #pragma unroll
        for (int j = 0; j < NTILES; ++j)
            if (nb[j] > lov) { psum += __uint_as_float(nb[j]); pcnt++; }
        #pragma unroll
        for (int off = 16; off > 0; off >>= 1) {
            psum += __shfl_down_sync(0xffffffffu, psum, off);
            pcnt += __shfl_down_sync(0xffffffffu, pcnt, off);
        }
        if (lane == 0) { sm.rf1[warp] = psum; sm.ri[warp] = pcnt; }
        __syncthreads();
        if (tid == 0) {
            double hs = 0.0; int cg = 0;
            #pragma unroll
            for (int w = 0; w < NW; ++w) { hs += (double)sm.rf1[w]; cg += sm.ri[w]; }
            hs += (double)(k - cg) * (double)V;
            atomicAdd(&g_hard_sum, hs);
        }
    }

    // ======== last-block finalize + self-reset =========================================
    if (tid == 0) {
        __threadfence();
        int ticket = atomicAdd(&g_done, 1);
        if (ticket == BB - 1) {
            double ps = atomicAdd(&g_pos_sum,  0.0);
            double hs = atomicAdd(&g_hard_sum, 0.0);
            double ls = atomicAdd(&g_loc_sum,  0.0);
            int    nn = atomicAdd(&g_npos_total, 0);
            double n  = (double)nn;
            out[0] = (float)((ps + hs) / n + ls / (n * 4.0));
            atomicExch((unsigned long long*)&g_pos_sum,  0ull);
            atomicExch((unsigned long long*)&g_hard_sum, 0ull);
            atomicExch((unsigned long long*)&g_loc_sum,  0ull);
            atomicExch(&g_npos_total, 0);
            __threadfence();
            atomicExch(&g_done, 0);
        }
    }
}

extern "C" void kernel_launch(void* const* d_in, const int* in_sizes, int n_in,
                              void* d_out, int out_size) {
    const float* locs   = (const float*)d_in[0];
    const float* scores = (const float*)d_in[1];
    const float* boxes  = (const float*)d_in[2];
    const int*   labels = (const int*)  d_in[3];
    const float* priors = (const float*)d_in[4];
    float* out = (float*)d_out;

    cudaFuncSetAttribute(mbl_kernel, cudaFuncAttributeMaxDynamicSharedMemorySize,
                         (int)sizeof(SmemLayout));
    mbl_kernel<<<BB, NT, sizeof(SmemLayout)>>>(locs, scores, boxes, labels, priors, out);
}

// round 16
// speedup vs baseline: 1.6409x; 1.0279x over previous
#include <cuda_runtime.h>
#include <cstdint>

#define BB 128
#define PP 8732
#define CC 21
#define OO 32
#define NT 768
#define NW 24
#define NCH 6           // pair-chunks of 2*NT priors (chunk 5: slot1 partial, 284 valid)
#define NTILES 12       // ceil(8732/768); tile 11 = 284 rows
#define TAILV (PP - 11 * NT)   // 284
#define KMASK 0xFFFFFFC0u      // top 26 bits of iou; low 6 = tie-break payload

typedef unsigned long long u64;

// ---------------- global accumulators (zero-init; self-resetting) ----------------
__device__ double g_pos_sum, g_loc_sum, g_hard_sum;
__device__ int    g_npos_total, g_done;

// ---------------- shared memory layout ----------------
struct __align__(16) SmemLayout {
    float  tile[2][NT * CC];            // 129024B double-buffered score tiles
    u64    wobj[NW * OO];               // per-warp per-object (masked_iou<<32)|~p
    unsigned wobj2[NW * NCH * OO];      // per-(warp,chunk,object) redux winner key
    float4 box[OO];
    float  area[OO];
    float  bcx[OO], bcy[OO], bw[OO], bh[OO];
    int    labels[OO];
    int    pfeo[OO];
    float  rf1[NW], rf2[NW];
    int    ri[NW];
    alignas(16) unsigned cntw[2][NW];
    int    npb;
    unsigned char ofep[PP];             // obj idx (0..31) | keep flag (bit 7)
};

__device__ __forceinline__ void cp_async16(uint32_t dst, const void* src) {
    asm volatile("cp.async.cg.shared.global [%0], [%1], 16;\n" :: "r"(dst), "l"(src));
}
__device__ __forceinline__ void cp_commit() { asm volatile("cp.async.commit_group;\n"); }
template <int N>
__device__ __forceinline__ void cp_wait() {
    asm volatile("cp.async.wait_group %0;\n" :: "n"(N));
}
__device__ __forceinline__ float frcp(float b) {
    float r;
    asm("rcp.approx.f32 %0, %1;" : "=f"(r) : "f"(b));
    return r;
}

// Pair-chunk matching (strides 2c, 2c+1). TAIL: slot1 valid only for tid < TAILV.
template <bool TAIL>
__device__ __forceinline__ void match_pair(SmemLayout& sm, const float4* __restrict__ pri4,
                                           int c, int tid, int warp, int lane,
                                           unsigned inv0, unsigned inv1, bool lp)
{
    const int base = c * 2 * NT;
    const bool v1 = !TAIL || (tid < TAILV);
    float4 p0 = pri4[base + tid];
    float4 p1 = v1 ? pri4[base + NT + tid] : make_float4(2e9f, 2e9f, 0.0f, 0.0f);
    const float ax0 = fmaf(p0.z, -0.5f, p0.x), ax1 = fmaf(p0.z, 0.5f, p0.x);
    const float ay0 = fmaf(p0.w, -0.5f, p0.y), ay1 = fmaf(p0.w, 0.5f, p0.y);
    const float apa = (ax1 - ax0) * (ay1 - ay0);
    const float cx0 = fmaf(p1.z, -0.5f, p1.x), cx1 = fmaf(p1.z, 0.5f, p1.x);
    const float cy0 = fmaf(p1.w, -0.5f, p1.y), cy1 = fmaf(p1.w, 0.5f, p1.y);
    const float cpa = (cx1 - cx0) * (cy1 - cy0);

    unsigned bibA = 0u, bibB = 0u;
    const int widx = (warp * NCH + c) * OO;

    #pragma unroll 8
    for (int o = 0; o < OO; ++o) {
        const float4 bx = sm.box[o];
        const float  ar = sm.area[o];
        // slot 0
        float lox = fmaxf(bx.x, ax0), loy = fmaxf(bx.y, ay0);
        float hix = fminf(bx.z, ax1), hiy = fminf(bx.w, ay1);
        float dx  = fmaxf(hix - lox, 0.0f), dy = fmaxf(hiy - loy, 0.0f);
        float in0 = dx * dy;
        float un0 = (apa + ar) - in0;
        unsigned u0 = __float_as_uint(in0 * frcp(un0));
        // slot 1
        lox = fmaxf(bx.x, cx0); loy = fmaxf(bx.y, cy0);
        hix = fminf(bx.z, cx1); hiy = fminf(bx.w, cy1);
        dx  = fmaxf(hix - lox, 0.0f); dy = fmaxf(hiy - loy, 0.0f);
        float in1 = dx * dy;
        float un1 = (cpa + ar) - in1;
        unsigned u1 = __float_as_uint(in1 * frcp(un1));

        bibA = max(bibA, (u0 & KMASK) | (unsigned)(63 - o));
        bibB = max(bibB, (u1 & KMASK) | (unsigned)(63 - o));

        unsigned km = max((u0 & KMASK) | inv0, (u1 & KMASK) | inv1);
        unsigned r  = __reduce_max_sync(0xffffffffu, km);
        if (lp) sm.wobj2[widx + o] = r;
    }
    sm.ofep[base + tid] =
        (unsigned char)((63 - (bibA & 63)) | (bibA >= 0x3F000000u ? 0x80 : 0));
    if (v1)
        sm.ofep[base + NT + tid] =
            (unsigned char)((63 - (bibB & 63)) | (bibB >= 0x3F000000u ? 0x80 : 0));
}

// Single-slot variant for tail warps with no valid slot1 priors (chunk 5, warp >= 9).
__device__ __forceinline__ void match_single(SmemLayout& sm, const float4* __restrict__ pri4,
                                             int c, int tid, int warp,
                                             unsigned inv0, bool lp)
{
    const int base = c * 2 * NT;
    float4 p0 = pri4[base + tid];
    const float ax0 = fmaf(p0.z, -0.5f, p0.x), ax1 = fmaf(p0.z, 0.5f, p0.x);
    const float ay0 = fmaf(p0.w, -0.5f, p0.y), ay1 = fmaf(p0.w, 0.5f, p0.y);
    const float apa = (ax1 - ax0) * (ay1 - ay0);

    unsigned bibA = 0u;
    const int widx = (warp * NCH + c) * OO;
    #pragma unroll 8
    for (int o = 0; o < OO; ++o) {
        const float4 bx = sm.box[o];
        const float  ar = sm.area[o];
        float lox = fmaxf(bx.x, ax0), loy = fmaxf(bx.y, ay0);
        float hix = fminf(bx.z, ax1), hiy = fminf(bx.w, ay1);
        float dx  = fmaxf(hix - lox, 0.0f), dy = fmaxf(hiy - loy, 0.0f);
        float in0 = dx * dy;
        float un0 = (apa + ar) - in0;
        unsigned u0 = __float_as_uint(in0 * frcp(un0));
        bibA = max(bibA, (u0 & KMASK) | (unsigned)(63 - o));
        unsigned r = __reduce_max_sync(0xffffffffu, (u0 & KMASK) | inv0);
        if (lp) sm.wobj2[widx + o] = r;
    }
    sm.ofep[base + tid] =
        (unsigned char)((63 - (bibA & 63)) | (bibA >= 0x3F000000u ? 0x80 : 0));
}

__global__ __launch_bounds__(NT)
void mbl_kernel(const float* __restrict__ locs,
                const float* __restrict__ scores,
                const float* __restrict__ boxes,
                const int*   __restrict__ labels,
                const float* __restrict__ priors,
                float*       __restrict__ out)
{
    extern __shared__ unsigned char smraw[];
    SmemLayout& sm = *reinterpret_cast<SmemLayout*>(smraw);

    const int b    = blockIdx.x;
    const int tid  = threadIdx.x;
    const int warp = tid >> 5;
    const int lane = tid & 31;
    const bool lp  = (lane == 0);
    const unsigned inv0 = (unsigned)(63 - lane);   // slot0: bit5 set
    const unsigned inv1 = (unsigned)(31 - lane);   // slot1

    if (tid < OO) {
        const float* bp = boxes + ((size_t)b * OO + tid) * 4;
        float x0 = bp[0], y0 = bp[1], x1 = bp[2], y1 = bp[3];
        sm.box[tid]  = make_float4(x0, y0, x1, y1);
        sm.area[tid] = (x1 - x0) * (y1 - y0);
        sm.bcx[tid] = (x0 + x1) * 0.5f;
        sm.bcy[tid] = (y0 + y1) * 0.5f;
        sm.bw[tid]  = x1 - x0;
        sm.bh[tid]  = y1 - y0;
        sm.labels[tid] = labels[(size_t)b * OO + tid];
    }
    __syncthreads();

    const float4* pri4  = reinterpret_cast<const float4*>(priors);
    const float4* locs4 = reinterpret_cast<const float4*>(locs);

    uint32_t tbase[2];
    tbase[0] = (uint32_t)__cvta_generic_to_shared(&sm.tile[0][0]);
    tbase[1] = (uint32_t)__cvta_generic_to_shared(&sm.tile[1][0]);

    // Per-warp staging: warp w copies ONLY its own 32 rows (2688B, 16B-aligned).
    auto issue_tile_w = [&](int t) {
        const int rowbase = t * NT + warp * 32;
        const int nrows   = min(32, PP - rowbase);
        if (nrows > 0) {
            const int nbytes = nrows * (CC * 4);
            const char* src = reinterpret_cast<const char*>(
                scores + ((size_t)b * PP + rowbase) * CC);
            const uint32_t dst = tbase[t & 1] + warp * (32 * CC * 4);
            for (int i = lane * 16; i < nbytes; i += 32 * 16)
                cp_async16(dst + i, src + i);
        }
        cp_commit();
    };
    issue_tile_w(0);
    issue_tile_w(1);

    unsigned nb[NTILES];
    auto lse_tile = [&](int t) -> unsigned {
        const float* row = &sm.tile[t & 1][tid * CC];
        float s0 = 0.0f, s1 = 0.0f, s2 = 0.0f;
        #pragma unroll
        for (int cc = 0; cc < 7; ++cc) {
            s0 += __expf(row[3 * cc]);
            s1 += __expf(row[3 * cc + 1]);
            s2 += __expf(row[3 * cc + 2]);
        }
        float conf = __logf(s0 + s1 + s2) - row[0];
        return (conf > 0.0f) ? __float_as_uint(conf) : 0u;
    };

    // ======== fused: matching chunk c -> CE tiles 2c, 2c+1 (warp-autonomous) =========
    #pragma unroll
    for (int c = 0; c < NCH; ++c) {
        if (c < NCH - 1) {
            match_pair<false>(sm, pri4, c, tid, warp, lane, inv0, inv1, lp);
        } else if (warp * 32 < TAILV) {               // warp-uniform split
            match_pair<true>(sm, pri4, c, tid, warp, lane, inv0, inv1, lp);
        } else {
            match_single(sm, pri4, c, tid, warp, inv0, lp);
        }

        cp_wait<1>(); __syncwarp();
        nb[2 * c] = lse_tile(2 * c);
        if (2 * c + 2 < NTILES) issue_tile_w(2 * c + 2);

        cp_wait<1>(); __syncwarp();
        if (2 * c + 1 == NTILES - 1)
            nb[2 * c + 1] = (tid < TAILV) ? lse_tile(2 * c + 1) : 0u;
        else
            nb[2 * c + 1] = lse_tile(2 * c + 1);
        if (2 * c + 3 < NTILES) issue_tile_w(2 * c + 3);
    }

    // ======== per-object resolution: chunk-scan -> 64-bit key -> cross-warp ==========
    __syncwarp();     // wobj2 rows are warp-private
    {
        const unsigned* rr = &sm.wobj2[warp * NCH * OO + lane];
        unsigned best = rr[0]; int bc = 0;
        #pragma unroll
        for (int c = 1; c < NCH; ++c) {
            unsigned r = rr[c * OO];
            if ((r & KMASK) > (best & KMASK)) { best = r; bc = c; }
        }
        int sdec = 1 - ((best >> 5) & 1);
        int p = bc * 2 * NT + sdec * NT + warp * 32 + (31 - (int)(best & 31));
        sm.wobj[warp * OO + lane] = ((u64)(best & KMASK) << 32) | (unsigned)(~p);
    }
    __syncthreads();
    if (tid < OO) {
        u64 bestk = sm.wobj[tid];
        #pragma unroll
        for (int w = 1; w < NW; ++w) {
            u64 k = sm.wobj[w * OO + tid];
            if (k > bestk) bestk = k;
        }
        sm.pfeo[tid] = (int)(~(unsigned)bestk);
    }
    __syncthreads();
    if (tid == 0) {            // sequential: last object wins on duplicate priors
        for (int o = 0; o < OO; ++o)
            sm.ofep[sm.pfeo[o]] = (unsigned char)(o | 0x80);
    }
    __syncthreads();

    // ======== positives post-pass: fix nb, accumulate posc/locsum/np =================
    float posc = 0.0f, locsum = 0.0f; int np = 0;
    #pragma unroll
    for (int j = 0; j < NTILES; ++j) {
        const int p = j * NT + tid;
        if (j < NTILES - 1 || tid < TAILV) {
            unsigned pk = sm.ofep[p];
            if (pk & 0x80) {
                int o   = pk & 31;
                int lab = sm.labels[o];
                if (lab != 0) {
                    const float* srow = scores + ((size_t)b * PP + p) * CC;
                    float r0 = __ldg(srow);
                    float rl = __ldg(srow + lab);
                    posc += __uint_as_float(nb[j]) + r0 - rl;
                    np++;
                    nb[j] = 0u;
                    float4 pr = pri4[p];
                    float rz = frcp(pr.z), rw = frcp(pr.w);
                    float gx = (sm.bcx[o] - pr.x) * 10.0f * rz;
                    float gy = (sm.bcy[o] - pr.y) * 10.0f * rw;
                    float gw = __logf(sm.bw[o] * rz) * 5.0f;
                    float gh = __logf(sm.bh[o] * rw) * 5.0f;
                    float4 pl = locs4[(size_t)b * PP + p];
                    locsum += fabsf(pl.x - gx) + fabsf(pl.y - gy)
                            + fabsf(pl.z - gw) + fabsf(pl.w - gh);
                }
            }
        }
    }

    // ---- block reduce np / posc / locsum ----
    #pragma unroll
    for (int off = 16; off > 0; off >>= 1) {
        posc   += __shfl_down_sync(0xffffffffu, posc,   off);
        locsum += __shfl_down_sync(0xffffffffu, locsum, off);
        np     += __shfl_down_sync(0xffffffffu, np,     off);
    }
    if (lane == 0) { sm.rf1[warp] = posc; sm.rf2[warp] = locsum; sm.ri[warp] = np; }
    __syncthreads();
    if (tid == 0) {
        float pc = 0.0f, ls = 0.0f; int n = 0;
        #pragma unroll
        for (int w = 0; w < NW; ++w) { pc += sm.rf1[w]; ls += sm.rf2[w]; n += sm.ri[w]; }
        sm.npb = n;
        atomicAdd(&g_npos_total, n);
        atomicAdd(&g_pos_sum, (double)pc);
        atomicAdd(&g_loc_sum, (double)ls);
    }
    __syncthreads();

    // ======== Exact top-k: ternary (2-probe) bit-pattern search =======================
    const int k = min(3 * sm.npb, PP);
    if (k > 0) {
        unsigned lo = 0u, hi = 0x42000000u;       // [0, 32): conf << 32 guaranteed
        for (int itr = 0; itr < 22 && (hi - lo) > 1u; ++itr) {
            unsigned d  = hi - lo;
            unsigned t1 = d / 3u; if (t1 == 0u) t1 = 1u;
            unsigned m1 = lo + t1;
            unsigned m2 = lo + 2u * t1;
            if (m2 >= hi) m2 = hi - 1u;
            if (m2 < m1)  m2 = m1;
            unsigned c = 0;
            #pragma unroll
            for (int j = 0; j < NTILES; ++j) {
                c += (nb[j] >= m1) ? 1u : 0u;
                c += (nb[j] >= m2) ? 0x10000u : 0u;
            }
            c = __reduce_add_sync(0xffffffffu, c);
            if (lane == 0) sm.cntw[itr & 1][warp] = c;
            __syncthreads();
            const uint4* c4 = reinterpret_cast<const uint4*>(sm.cntw[itr & 1]);
            unsigned tot = 0;
            #pragma unroll
            for (int i = 0; i < NW / 4; ++i) {
                uint4 v = c4[i];
                tot += v.x + v.y + v.z + v.w;
            }
            const int c1 = (int)(tot & 0xFFFFu);
            const int c2 = (int)(tot >> 16);
            if (c2 >= k)      lo = m2;
            else if (c1 >= k) { lo = m1; hi = m2; }
            else              hi = m1;
        }
        const unsigned lov = lo;
        const float V = __uint_as_float(lov);
        float psum = 0.0f; int pcnt = 0;
        #pragma unroll
        for (int j = 0; j < NTILES; ++j)
            if (nb[j] > lov) { psum += __uint_as_float(nb[j]); pcnt++; }
        #pragma unroll
        for (int off = 16; off > 0; off >>= 1) {
            psum += __shfl_down_sync(0xffffffffu, psum, off);
            pcnt += __shfl_down_sync(0xffffffffu, pcnt, off);
        }
        if (lane == 0) { sm.rf1[warp] = psum; sm.ri[warp] = pcnt; }
        __syncthreads();
        if (tid == 0) {
            double hs = 0.0; int cg = 0;
            #pragma unroll
            for (int w = 0; w < NW; ++w) { hs += (double)sm.rf1[w]; cg += sm.ri[w]; }
            hs += (double)(k - cg) * (double)V;
            atomicAdd(&g_hard_sum, hs);
        }
    }

    // ======== last-block finalize + self-reset =========================================
    if (tid == 0) {
        __threadfence();
        int ticket = atomicAdd(&g_done, 1);
        if (ticket == BB - 1) {
            double ps = atomicAdd(&g_pos_sum,  0.0);
            double hs = atomicAdd(&g_hard_sum, 0.0);
            double ls = atomicAdd(&g_loc_sum,  0.0);
            int    nn = atomicAdd(&g_npos_total, 0);
            double n  = (double)nn;
            out[0] = (float)((ps + hs) / n + ls / (n * 4.0));
            atomicExch((unsigned long long*)&g_pos_sum,  0ull);
            atomicExch((unsigned long long*)&g_hard_sum, 0ull);
            atomicExch((unsigned long long*)&g_loc_sum,  0ull);
            atomicExch(&g_npos_total, 0);
            __threadfence();
            atomicExch(&g_done, 0);
        }
    }
}

extern "C" void kernel_launch(void* const* d_in, const int* in_sizes, int n_in,
                              void* d_out, int out_size) {
    const float* locs   = (const float*)d_in[0];
    const float* scores = (const float*)d_in[1];
    const float* boxes  = (const float*)d_in[2];
    const int*   labels = (const int*)  d_in[3];
    const float* priors = (const float*)d_in[4];
    float* out = (float*)d_out;

    cudaFuncSetAttribute(mbl_kernel, cudaFuncAttributeMaxDynamicSharedMemorySize,
                         (int)sizeof(SmemLayout));
    mbl_kernel<<<BB, NT, sizeof(SmemLayout)>>>(locs, scores, boxes, labels, priors, out);
}

// round 17
// speedup vs baseline: 1.7169x; 1.0463x over previous
#include <cuda_runtime.h>
#include <cstdint>

#define BB 128
#define PP 8732
#define CC 21
#define OO 32
#define NT 768
#define NW 24
#define NCH 6           // pair-chunks of 2*NT priors (chunk 5: slot1 partial, 284 valid)
#define NTILES 12       // ceil(8732/768); tile 11 = 284 rows
#define TAILV (PP - 11 * NT)   // 284
#define KMASK 0xFFFFFFC0u      // top 26 bits of r=in/S; low 6 = tie-break payload
#define TKEEP 0x3EAAAA80u      // bits(1/3) & KMASK : r >= 1/3  <=>  iou >= 0.5

typedef unsigned long long u64;

// ---------------- global accumulators (zero-init; self-resetting) ----------------
__device__ double g_pos_sum, g_loc_sum, g_hard_sum;
__device__ int    g_npos_total, g_done;

// ---------------- shared memory layout ----------------
struct __align__(16) SmemLayout {
    float  tile[2][NT * CC];            // 129024B double-buffered score tiles
    u64    wobj[NW * OO];               // per-warp per-object (masked_r<<32)|~p
    unsigned wobj2[NW * NCH * OO];      // per-(warp,chunk,object) redux winner key
    float4 box[OO];
    float  area[OO];
    float  bcx[OO], bcy[OO], bw[OO], bh[OO];
    int    labels[OO];
    int    pfeo[OO];
    float  rf1[NW], rf2[NW];
    int    ri[NW];
    alignas(16) unsigned cntw[2][NW];
    int    npb;
    unsigned char ofep[PP];             // obj idx (0..31) | keep flag (bit 7)
};

__device__ __forceinline__ void cp_async16(uint32_t dst, const void* src) {
    asm volatile("cp.async.cg.shared.global [%0], [%1], 16;\n" :: "r"(dst), "l"(src));
}
__device__ __forceinline__ void cp_commit() { asm volatile("cp.async.commit_group;\n"); }
template <int N>
__device__ __forceinline__ void cp_wait() {
    asm volatile("cp.async.wait_group %0;\n" :: "n"(N));
}
__device__ __forceinline__ float frcp(float b) {
    float r;
    asm("rcp.approx.f32 %0, %1;" : "=f"(r) : "f"(b));
    return r;
}

// Pair-chunk matching (strides 2c, 2c+1). TAIL: slot1 valid only for tid < TAILV.
// Key = r = in/S, S = pa+ar: order-equivalent to iou (iou = r/(1-r), monotone).
template <bool TAIL>
__device__ __forceinline__ void match_pair(SmemLayout& sm, const float4* __restrict__ pri4,
                                           int c, int tid, int warp, int lane,
                                           unsigned inv0, unsigned inv1, bool lp)
{
    const int base = c * 2 * NT;
    const bool v1 = !TAIL || (tid < TAILV);
    float4 p0 = pri4[base + tid];
    float4 p1 = v1 ? pri4[base + NT + tid] : make_float4(2e9f, 2e9f, 0.0f, 0.0f);
    const float ax0 = fmaf(p0.z, -0.5f, p0.x), ax1 = fmaf(p0.z, 0.5f, p0.x);
    const float ay0 = fmaf(p0.w, -0.5f, p0.y), ay1 = fmaf(p0.w, 0.5f, p0.y);
    const float apa = (ax1 - ax0) * (ay1 - ay0);
    const float cx0 = fmaf(p1.z, -0.5f, p1.x), cx1 = fmaf(p1.z, 0.5f, p1.x);
    const float cy0 = fmaf(p1.w, -0.5f, p1.y), cy1 = fmaf(p1.w, 0.5f, p1.y);
    const float cpa = (cx1 - cx0) * (cy1 - cy0);

    unsigned bibA = 0u, bibB = 0u;
    const int widx = (warp * NCH + c) * OO;

    #pragma unroll 8
    for (int o = 0; o < OO; ++o) {
        const float4 bx = sm.box[o];
        const float  ar = sm.area[o];
        // slot 0
        float lox = fmaxf(bx.x, ax0), loy = fmaxf(bx.y, ay0);
        float hix = fminf(bx.z, ax1), hiy = fminf(bx.w, ay1);
        float dx  = fmaxf(hix - lox, 0.0f), dy = fmaxf(hiy - loy, 0.0f);
        float in0 = dx * dy;
        unsigned u0 = __float_as_uint(in0 * frcp(apa + ar));
        // slot 1
        lox = fmaxf(bx.x, cx0); loy = fmaxf(bx.y, cy0);
        hix = fminf(bx.z, cx1); hiy = fminf(bx.w, cy1);
        dx  = fmaxf(hix - lox, 0.0f); dy = fmaxf(hiy - loy, 0.0f);
        float in1 = dx * dy;
        unsigned u1 = __float_as_uint(in1 * frcp(cpa + ar));

        bibA = max(bibA, (u0 & KMASK) | (unsigned)(63 - o));
        bibB = max(bibB, (u1 & KMASK) | (unsigned)(63 - o));

        unsigned km = max((u0 & KMASK) | inv0, (u1 & KMASK) | inv1);
        unsigned r  = __reduce_max_sync(0xffffffffu, km);
        if (lp) sm.wobj2[widx + o] = r;
    }
    sm.ofep[base + tid] =
        (unsigned char)((63 - (bibA & 63)) | (bibA >= TKEEP ? 0x80 : 0));
    if (v1)
        sm.ofep[base + NT + tid] =
            (unsigned char)((63 - (bibB & 63)) | (bibB >= TKEEP ? 0x80 : 0));
}

// Single-slot variant for tail warps with no valid slot1 priors (chunk 5, warp >= 9).
__device__ __forceinline__ void match_single(SmemLayout& sm, const float4* __restrict__ pri4,
                                             int c, int tid, int warp,
                                             unsigned inv0, bool lp)
{
    const int base = c * 2 * NT;
    float4 p0 = pri4[base + tid];
    const float ax0 = fmaf(p0.z, -0.5f, p0.x), ax1 = fmaf(p0.z, 0.5f, p0.x);
    const float ay0 = fmaf(p0.w, -0.5f, p0.y), ay1 = fmaf(p0.w, 0.5f, p0.y);
    const float apa = (ax1 - ax0) * (ay1 - ay0);

    unsigned bibA = 0u;
    const int widx = (warp * NCH + c) * OO;
    #pragma unroll 8
    for (int o = 0; o < OO; ++o) {
        const float4 bx = sm.box[o];
        const float  ar = sm.area[o];
        float lox = fmaxf(bx.x, ax0), loy = fmaxf(bx.y, ay0);
        float hix = fminf(bx.z, ax1), hiy = fminf(bx.w, ay1);
        float dx  = fmaxf(hix - lox, 0.0f), dy = fmaxf(hiy - loy, 0.0f);
        float in0 = dx * dy;
        unsigned u0 = __float_as_uint(in0 * frcp(apa + ar));
        bibA = max(bibA, (u0 & KMASK) | (unsigned)(63 - o));
        unsigned r = __reduce_max_sync(0xffffffffu, (u0 & KMASK) | inv0);
        if (lp) sm.wobj2[widx + o] = r;
    }
    sm.ofep[base + tid] =
        (unsigned char)((63 - (bibA & 63)) | (bibA >= TKEEP ? 0x80 : 0));
}

__global__ __launch_bounds__(NT)
void mbl_kernel(const float* __restrict__ locs,
                const float* __restrict__ scores,
                const float* __restrict__ boxes,
                const int*   __restrict__ labels,
                const float* __restrict__ priors,
                float*       __restrict__ out)
{
    extern __shared__ unsigned char smraw[];
    SmemLayout& sm = *reinterpret_cast<SmemLayout*>(smraw);

    const int b    = blockIdx.x;
    const int tid  = threadIdx.x;
    const int warp = tid >> 5;
    const int lane = tid & 31;
    const bool lp  = (lane == 0);
    const unsigned inv0 = (unsigned)(63 - lane);   // slot0: bit5 set
    const unsigned inv1 = (unsigned)(31 - lane);   // slot1

    if (tid < OO) {
        const float* bp = boxes + ((size_t)b * OO + tid) * 4;
        float x0 = bp[0], y0 = bp[1], x1 = bp[2], y1 = bp[3];
        sm.box[tid]  = make_float4(x0, y0, x1, y1);
        sm.area[tid] = (x1 - x0) * (y1 - y0);
        sm.bcx[tid] = (x0 + x1) * 0.5f;
        sm.bcy[tid] = (y0 + y1) * 0.5f;
        sm.bw[tid]  = x1 - x0;
        sm.bh[tid]  = y1 - y0;
        sm.labels[tid] = labels[(size_t)b * OO + tid];
    }
    __syncthreads();

    const float4* pri4  = reinterpret_cast<const float4*>(priors);
    const float4* locs4 = reinterpret_cast<const float4*>(locs);

    uint32_t tbase[2];
    tbase[0] = (uint32_t)__cvta_generic_to_shared(&sm.tile[0][0]);
    tbase[1] = (uint32_t)__cvta_generic_to_shared(&sm.tile[1][0]);

    // Per-warp staging: warp w copies ONLY its own 32 rows (2688B, 16B-aligned).
    auto issue_tile_w = [&](int t) {
        const int rowbase = t * NT + warp * 32;
        const int nrows   = min(32, PP - rowbase);
        if (nrows > 0) {
            const int nbytes = nrows * (CC * 4);
            const char* src = reinterpret_cast<const char*>(
                scores + ((size_t)b * PP + rowbase) * CC);
            const uint32_t dst = tbase[t & 1] + warp * (32 * CC * 4);
            for (int i = lane * 16; i < nbytes; i += 32 * 16)
                cp_async16(dst + i, src + i);
        }
        cp_commit();
    };
    issue_tile_w(0);
    issue_tile_w(1);

    unsigned nb[NTILES];
    auto lse_tile = [&](int t) -> unsigned {
        const float* row = &sm.tile[t & 1][tid * CC];
        float s0 = 0.0f, s1 = 0.0f, s2 = 0.0f;
        #pragma unroll
        for (int cc = 0; cc < 7; ++cc) {
            s0 += __expf(row[3 * cc]);
            s1 += __expf(row[3 * cc + 1]);
            s2 += __expf(row[3 * cc + 2]);
        }
        float conf = __logf(s0 + s1 + s2) - row[0];
        return (conf > 0.0f) ? __float_as_uint(conf) : 0u;
    };

    // ======== fused: matching chunk c -> CE tiles 2c, 2c+1 (warp-autonomous) =========
    #pragma unroll
    for (int c = 0; c < NCH; ++c) {
        if (c < NCH - 1) {
            match_pair<false>(sm, pri4, c, tid, warp, lane, inv0, inv1, lp);
        } else if (warp * 32 < TAILV) {               // warp-uniform split
            match_pair<true>(sm, pri4, c, tid, warp, lane, inv0, inv1, lp);
        } else {
            match_single(sm, pri4, c, tid, warp, inv0, lp);
        }

        cp_wait<1>(); __syncwarp();
        nb[2 * c] = lse_tile(2 * c);
        if (2 * c + 2 < NTILES) issue_tile_w(2 * c + 2);

        cp_wait<1>(); __syncwarp();
        if (2 * c + 1 == NTILES - 1)
            nb[2 * c + 1] = (tid < TAILV) ? lse_tile(2 * c + 1) : 0u;
        else
            nb[2 * c + 1] = lse_tile(2 * c + 1);
        if (2 * c + 3 < NTILES) issue_tile_w(2 * c + 3);
    }

    // ======== per-object resolution: chunk-scan -> 64-bit key -> cross-warp ==========
    __syncwarp();     // wobj2 rows are warp-private
    {
        const unsigned* rr = &sm.wobj2[warp * NCH * OO + lane];
        unsigned best = rr[0]; int bc = 0;
        #pragma unroll
        for (int c = 1; c < NCH; ++c) {
            unsigned r = rr[c * OO];
            if ((r & KMASK) > (best & KMASK)) { best = r; bc = c; }
        }
        int sdec = 1 - ((best >> 5) & 1);
        int p = bc * 2 * NT + sdec * NT + warp * 32 + (31 - (int)(best & 31));
        sm.wobj[warp * OO + lane] = ((u64)(best & KMASK) << 32) | (unsigned)(~p);
    }
    __syncthreads();
    if (tid < OO) {
        u64 bestk = sm.wobj[tid];
        #pragma unroll
        for (int w = 1; w < NW; ++w) {
            u64 k = sm.wobj[w * OO + tid];
            if (k > bestk) bestk = k;
        }
        sm.pfeo[tid] = (int)(~(unsigned)bestk);
    }
    __syncthreads();
    if (tid == 0) {            // sequential: last object wins on duplicate priors
        for (int o = 0; o < OO; ++o)
            sm.ofep[sm.pfeo[o]] = (unsigned char)(o | 0x80);
    }
    __syncthreads();

    // ======== positives post-pass: fix nb, accumulate posc/locsum/np =================
    float posc = 0.0f, locsum = 0.0f; int np = 0;
    #pragma unroll
    for (int j = 0; j < NTILES; ++j) {
        const int p = j * NT + tid;
        if (j < NTILES - 1 || tid < TAILV) {
            unsigned pk = sm.ofep[p];
            if (pk & 0x80) {
                int o   = pk & 31;
                int lab = sm.labels[o];
                if (lab != 0) {
                    const float* srow = scores + ((size_t)b * PP + p) * CC;
                    float r0 = __ldg(srow);
                    float rl = __ldg(srow + lab);
                    posc += __uint_as_float(nb[j]) + r0 - rl;
                    np++;
                    nb[j] = 0u;
                    float4 pr = pri4[p];
                    float rz = frcp(pr.z), rw = frcp(pr.w);
                    float gx = (sm.bcx[o] - pr.x) * 10.0f * rz;
                    float gy = (sm.bcy[o] - pr.y) * 10.0f * rw;
                    float gw = __logf(sm.bw[o] * rz) * 5.0f;
                    float gh = __logf(sm.bh[o] * rw) * 5.0f;
                    float4 pl = locs4[(size_t)b * PP + p];
                    locsum += fabsf(pl.x - gx) + fabsf(pl.y - gy)
                            + fabsf(pl.z - gw) + fabsf(pl.w - gh);
                }
            }
        }
    }

    // ---- block reduce np / posc / locsum ----
    #pragma unroll
    for (int off = 16; off > 0; off >>= 1) {
        posc   += __shfl_down_sync(0xffffffffu, posc,   off);
        locsum += __shfl_down_sync(0xffffffffu, locsum, off);
        np     += __shfl_down_sync(0xffffffffu, np,     off);
    }
    if (lane == 0) { sm.rf1[warp] = posc; sm.rf2[warp] = locsum; sm.ri[warp] = np; }
    __syncthreads();
    if (tid == 0) {
        float pc = 0.0f, ls = 0.0f; int n = 0;
        #pragma unroll
        for (int w = 0; w < NW; ++w) { pc += sm.rf1[w]; ls += sm.rf2[w]; n += sm.ri[w]; }
        sm.npb = n;
        atomicAdd(&g_npos_total, n);
        atomicAdd(&g_pos_sum, (double)pc);
        atomicAdd(&g_loc_sum, (double)ls);
    }
    __syncthreads();

    // ======== Exact top-k: ternary (2-probe) search with exact early-exit =============
    const int k = min(3 * sm.npb, PP);
    if (k > 0) {
        unsigned lo = 0u, hi = 0x42000000u;       // [0, 32): conf << 32 guaranteed
        for (int itr = 0; itr < 22 && (hi - lo) > 1u; ++itr) {
            unsigned d  = hi - lo;
            unsigned t1 = d / 3u; if (t1 == 0u) t1 = 1u;
            unsigned m1 = lo + t1;
            unsigned m2 = lo + 2u * t1;
            if (m2 >= hi) m2 = hi - 1u;
            if (m2 < m1)  m2 = m1;
            unsigned c = 0;
            #pragma unroll
            for (int j = 0; j < NTILES; ++j) {
                c += (nb[j] >= m1) ? 1u : 0u;
                c += (nb[j] >= m2) ? 0x10000u : 0u;
            }
            c = __reduce_add_sync(0xffffffffu, c);
            if (lane == 0) sm.cntw[itr & 1][warp] = c;
            __syncthreads();
            const uint4* c4 = reinterpret_cast<const uint4*>(sm.cntw[itr & 1]);
            unsigned tot = 0;
            #pragma unroll
            for (int i = 0; i < NW / 4; ++i) {
                uint4 v = c4[i];
                tot += v.x + v.y + v.z + v.w;
            }
            const int c1 = (int)(tot & 0xFFFFu);
            const int c2 = (int)(tot >> 16);
            if (c2 == k)      { lo = m2; break; }   // exact: cnt_ge(lo)==k suffices
            if (c1 == k)      { lo = m1; break; }
            if (c2 > k)       lo = m2;
            else if (c1 > k)  { lo = m1; hi = m2; }
            else              hi = m1;
        }
        const unsigned lov = lo;
        const float V = __uint_as_float(lov);
        float psum = 0.0f; int pcnt = 0;
        #pragma unroll
        for (int j = 0; j < NTILES; ++j)
            if (nb[j] > lov) { psum += __uint_as_float(nb[j]); pcnt++; }
        #pragma unroll
        for (int off = 16; off > 0; off >>= 1) {
            psum += __shfl_down_sync(0xffffffffu, psum, off);
            pcnt += __shfl_down_sync(0xffffffffu, pcnt, off);
        }
        if (lane == 0) { sm.rf1[warp] = psum; sm.ri[warp] = pcnt; }
        __syncthreads();
        if (tid == 0) {
            double hs = 0.0; int cg = 0;
            #pragma unroll
            for (int w = 0; w < NW; ++w) { hs += (double)sm.rf1[w]; cg += sm.ri[w]; }
            hs += (double)(k - cg) * (double)V;
            atomicAdd(&g_hard_sum, hs);
        }
    }

    // ======== last-block finalize + self-reset =========================================
    if (tid == 0) {
        __threadfence();
        int ticket = atomicAdd(&g_done, 1);
        if (ticket == BB - 1) {
            double ps = atomicAdd(&g_pos_sum,  0.0);
            double hs = atomicAdd(&g_hard_sum, 0.0);
            double ls = atomicAdd(&g_loc_sum,  0.0);
            int    nn = atomicAdd(&g_npos_total, 0);
            double n  = (double)nn;
            out[0] = (float)((ps + hs) / n + ls / (n * 4.0));
            atomicExch((unsigned long long*)&g_pos_sum,  0ull);
            atomicExch((unsigned long long*)&g_hard_sum, 0ull);
            atomicExch((unsigned long long*)&g_loc_sum,  0ull);
            atomicExch(&g_npos_total, 0);
            __threadfence();
            atomicExch(&g_done, 0);
        }
    }
}

extern "C" void kernel_launch(void* const* d_in, const int* in_sizes, int n_in,
                              void* d_out, int out_size) {
    const float* locs   = (const float*)d_in[0];
    const float* scores = (const float*)d_in[1];
    const float* boxes  = (const float*)d_in[2];
    const int*   labels = (const int*)  d_in[3];
    const float* priors = (const float*)d_in[4];
    float* out = (float*)d_out;

    cudaFuncSetAttribute(mbl_kernel, cudaFuncAttributeMaxDynamicSharedMemorySize,
                         (int)sizeof(SmemLayout));
    mbl_kernel<<<BB, NT, sizeof(SmemLayout)>>>(locs, scores, boxes, labels, priors, out);
}